// round 1
// baseline (speedup 1.0000x reference)
#include <cuda_runtime.h>

#define HD   128
#define BB   64
#define LQ   64
#define LDOC 4096
#define TOK  32
#define LN_EPS 1e-5f
#define NEGV  -1e30f
#define DCH  256
#define NCH  (LDOC / DCH)   // 16
#define SUBD 64

// scratch (no cudaMalloc allowed)
__device__ float g_dv[(size_t)BB * LDOC * HD];   // 134 MB
__device__ float g_qv[(size_t)BB * LQ * HD];     // 2 MB
__device__ float g_pmax[(size_t)BB * NCH * LQ];  // 256 KB

__device__ __forceinline__ float warp_allreduce_sum(float v) {
#pragma unroll
    for (int o = 16; o > 0; o >>= 1) v += __shfl_xor_sync(0xffffffffu, v, o);
    return v;
}

// One MLP layer + ReLU + LayerNorm for 32 tokens.
// Thread layout: warp w owns tokens m0=8w..8w+7; lane l owns columns 4l..4l+3.
// sW: weights [k][j] row-major (HD*HD floats). sx: activations [m][k] (TOK*HD).
template <bool FINAL>
__device__ __forceinline__ void do_layer(
    const float* __restrict__ sW, float* __restrict__ sx,
    const float* __restrict__ bias, float4 wln, float4 bln,
    int lane, int m0,
    const int* __restrict__ mask, long base, float* __restrict__ gout)
{
    float acc[8][4];
#pragma unroll
    for (int mi = 0; mi < 8; mi++) {
        acc[mi][0] = 0.f; acc[mi][1] = 0.f; acc[mi][2] = 0.f; acc[mi][3] = 0.f;
    }

#pragma unroll 4
    for (int k = 0; k < HD; k += 2) {
        const float4 wA = *(const float4*)(sW + (k    ) * HD + 4 * lane);
        const float4 wB = *(const float4*)(sW + (k + 1) * HD + 4 * lane);
#pragma unroll
        for (int mi = 0; mi < 8; mi++) {
            const float2 xv = *(const float2*)(sx + (m0 + mi) * HD + k);
            acc[mi][0] += xv.x * wA.x; acc[mi][1] += xv.x * wA.y;
            acc[mi][2] += xv.x * wA.z; acc[mi][3] += xv.x * wA.w;
            acc[mi][0] += xv.y * wB.x; acc[mi][1] += xv.y * wB.y;
            acc[mi][2] += xv.y * wB.z; acc[mi][3] += xv.y * wB.w;
        }
    }

    const float4 bj = *(const float4*)(bias + 4 * lane);
    float res[8][4];
#pragma unroll
    for (int mi = 0; mi < 8; mi++) {
        const float v0 = fmaxf(acc[mi][0] + bj.x, 0.f);
        const float v1 = fmaxf(acc[mi][1] + bj.y, 0.f);
        const float v2 = fmaxf(acc[mi][2] + bj.z, 0.f);
        const float v3 = fmaxf(acc[mi][3] + bj.w, 0.f);
        const float s  = warp_allreduce_sum(v0 + v1 + v2 + v3);
        const float sq = warp_allreduce_sum(v0 * v0 + v1 * v1 + v2 * v2 + v3 * v3);
        const float mean = s * (1.0f / HD);
        const float var  = sq * (1.0f / HD) - mean * mean;
        const float rstd = rsqrtf(var + LN_EPS);
        res[mi][0] = (v0 - mean) * rstd * wln.x + bln.x;
        res[mi][1] = (v1 - mean) * rstd * wln.y + bln.y;
        res[mi][2] = (v2 - mean) * rstd * wln.z + bln.z;
        res[mi][3] = (v3 - mean) * rstd * wln.w + bln.w;
    }

    if (FINAL) {
#pragma unroll
        for (int mi = 0; mi < 8; mi++) {
            const long tok = base + m0 + mi;
            const float mv = (float)mask[tok];
            *(float4*)(gout + (size_t)tok * HD + 4 * lane) =
                make_float4(res[mi][0] * mv, res[mi][1] * mv,
                            res[mi][2] * mv, res[mi][3] * mv);
        }
    } else {
        // only this warp reads/writes rows m0..m0+7 of sx -> no block sync needed
#pragma unroll
        for (int mi = 0; mi < 8; mi++) {
            *(float4*)(sx + (m0 + mi) * HD + 4 * lane) =
                make_float4(res[mi][0], res[mi][1], res[mi][2], res[mi][3]);
        }
    }
}

__global__ __launch_bounds__(128, 2)
void encode_kernel(const int* __restrict__ ids, const int* __restrict__ mask,
                   const float* __restrict__ emb,
                   const float* __restrict__ W1, const float* __restrict__ b1,
                   const float* __restrict__ W2, const float* __restrict__ b2,
                   const float* __restrict__ lnw, const float* __restrict__ lnb,
                   int which)  // 0 -> g_dv, 1 -> g_qv
{
    extern __shared__ float smem[];
    float* sW = smem;             // HD*HD   (64 KB)
    float* sx = smem + HD * HD;   // TOK*HD  (16 KB)

    float* gout = which ? g_qv : g_dv;
    const int t    = threadIdx.x;
    const int lane = t & 31;
    const int wrp  = t >> 5;
    const int m0   = wrp * 8;
    const long base = (long)blockIdx.x * TOK;

    // gather embeddings into sx[m][k]; 4 threads per token
    {
        const int m = t >> 2, p = t & 3;
        const int id = ids[base + m];
        const float4* src = (const float4*)(emb + (size_t)id * HD) + p * 8;
        float4* dst = (float4*)(sx + m * HD) + p * 8;
#pragma unroll
        for (int r = 0; r < 8; r++) dst[r] = src[r];
    }

    const float4 wln = *(const float4*)(lnw + 4 * lane);
    const float4 bln = *(const float4*)(lnb + 4 * lane);

    // load W1 into SMEM
    {
        const float4* src = (const float4*)W1;
        float4* dst = (float4*)sW;
#pragma unroll
        for (int i = 0; i < 32; i++) dst[t + i * 128] = src[t + i * 128];
    }
    __syncthreads();

    do_layer<false>(sW, sx, b1, wln, bln, lane, m0, mask, base, gout);

    __syncthreads();   // all warps done with W1 + sx rewritten
    // load W2 into SMEM
    {
        const float4* src = (const float4*)W2;
        float4* dst = (float4*)sW;
#pragma unroll
        for (int i = 0; i < 32; i++) dst[t + i * 128] = src[t + i * 128];
    }
    __syncthreads();

    do_layer<true>(sW, sx, b2, wln, bln, lane, m0, mask, base, gout);
}

__global__ __launch_bounds__(256, 2)
void sim_kernel(const int* __restrict__ dmask)
{
    extern __shared__ float smem[];
    float* sq   = smem;                 // [HD][64] transposed query tile
    float* sd   = smem + HD * 64;       // [HD][64] transposed doc tile
    float* sred = smem + 2 * HD * 64;   // [64][17]

    const int b  = blockIdx.x;
    const int ch = blockIdx.y;
    const int t  = threadIdx.x;
    const int tq = t & 15;   // q0 = 4*tq
    const int td = t >> 4;   // d0 = 4*td

    // load qv[b] transposed into sq[h][q]
    {
        const float* qv = g_qv + (size_t)b * LQ * HD;
        const int q = t >> 2, p = t & 3;
#pragma unroll
        for (int r = 0; r < 8; r++) {
            const int h4 = p * 8 + r;
            const float4 v = ((const float4*)(qv + q * HD))[h4];
            sq[(h4 * 4 + 0) * 64 + q] = v.x;
            sq[(h4 * 4 + 1) * 64 + q] = v.y;
            sq[(h4 * 4 + 2) * 64 + q] = v.z;
            sq[(h4 * 4 + 3) * 64 + q] = v.w;
        }
    }

    float rmax[4] = {-3.0e38f, -3.0e38f, -3.0e38f, -3.0e38f};

    for (int s = 0; s < DCH / SUBD; s++) {
        __syncthreads();   // prev subtile reads done (also covers sq init at s=0)
        {
            const size_t dbase = (size_t)b * LDOC + (size_t)ch * DCH + s * SUBD;
            const int d = t >> 2, p = t & 3;
            const float* dvp = g_dv + (dbase + d) * HD;
#pragma unroll
            for (int r = 0; r < 8; r++) {
                const int h4 = p * 8 + r;
                const float4 v = ((const float4*)dvp)[h4];
                sd[(h4 * 4 + 0) * 64 + d] = v.x;
                sd[(h4 * 4 + 1) * 64 + d] = v.y;
                sd[(h4 * 4 + 2) * 64 + d] = v.z;
                sd[(h4 * 4 + 3) * 64 + d] = v.w;
            }
        }
        __syncthreads();

        float acc[4][4];
#pragma unroll
        for (int i = 0; i < 4; i++)
#pragma unroll
            for (int j = 0; j < 4; j++) acc[i][j] = 0.f;

#pragma unroll 4
        for (int h = 0; h < HD; h++) {
            const float4 q4 = *(const float4*)(sq + h * 64 + 4 * tq);
            const float4 d4 = *(const float4*)(sd + h * 64 + 4 * td);
            acc[0][0] += q4.x * d4.x; acc[0][1] += q4.x * d4.y;
            acc[0][2] += q4.x * d4.z; acc[0][3] += q4.x * d4.w;
            acc[1][0] += q4.y * d4.x; acc[1][1] += q4.y * d4.y;
            acc[1][2] += q4.y * d4.z; acc[1][3] += q4.y * d4.w;
            acc[2][0] += q4.z * d4.x; acc[2][1] += q4.z * d4.y;
            acc[2][2] += q4.z * d4.z; acc[2][3] += q4.z * d4.w;
            acc[3][0] += q4.w * d4.x; acc[3][1] += q4.w * d4.y;
            acc[3][2] += q4.w * d4.z; acc[3][3] += q4.w * d4.w;
        }

        const int dglob0 = ch * DCH + s * SUBD + 4 * td;
#pragma unroll
        for (int j = 0; j < 4; j++) {
            const float penalty =
                (1.0f - (float)dmask[(size_t)b * LDOC + dglob0 + j]) * NEGV;
#pragma unroll
            for (int i = 0; i < 4; i++)
                rmax[i] = fmaxf(rmax[i], acc[i][j] + penalty);
        }
    }

    // reduce max across the 16 td groups
#pragma unroll
    for (int i = 0; i < 4; i++) sred[(4 * tq + i) * 17 + td] = rmax[i];
    __syncthreads();
    if (t < 64) {
        float m = -3.0e38f;
#pragma unroll
        for (int j = 0; j < 16; j++) m = fmaxf(m, sred[t * 17 + j]);
        g_pmax[((size_t)b * NCH + ch) * LQ + t] = m;
    }
}

__global__ void final_kernel(float* __restrict__ out)
{
    const int b = blockIdx.x;
    const int q = threadIdx.x;  // 64 threads
    float m = -3.0e38f;
#pragma unroll
    for (int ch = 0; ch < NCH; ch++)
        m = fmaxf(m, g_pmax[((size_t)b * NCH + ch) * LQ + q]);
    float s = m;
#pragma unroll
    for (int o = 16; o > 0; o >>= 1) s += __shfl_xor_sync(0xffffffffu, s, o);
    __shared__ float sp[2];
    if ((q & 31) == 0) sp[q >> 5] = s;
    __syncthreads();
    if (q == 0) out[b] = sp[0] + sp[1];
}

extern "C" void kernel_launch(void* const* d_in, const int* in_sizes, int n_in,
                              void* d_out, int out_size)
{
    const int*   qids   = (const int*)d_in[0];
    const int*   dids   = (const int*)d_in[1];
    const int*   qmask  = (const int*)d_in[2];
    const int*   dmask  = (const int*)d_in[3];
    const float* q_emb  = (const float*)d_in[4];
    const float* qW1    = (const float*)d_in[5];
    const float* qb1    = (const float*)d_in[6];
    const float* qW2    = (const float*)d_in[7];
    const float* qb2    = (const float*)d_in[8];
    const float* q_lnw  = (const float*)d_in[9];
    const float* q_lnb  = (const float*)d_in[10];
    const float* d_emb  = (const float*)d_in[11];
    const float* dW1    = (const float*)d_in[12];
    const float* db1    = (const float*)d_in[13];
    const float* dW2    = (const float*)d_in[14];
    const float* db2    = (const float*)d_in[15];
    const float* d_lnw  = (const float*)d_in[16];
    const float* d_lnb  = (const float*)d_in[17];
    float* out = (float*)d_out;

    const int smemE = (HD * HD + TOK * HD) * (int)sizeof(float);          // 80 KB
    const int smemS = (2 * HD * 64 + 64 * 17) * (int)sizeof(float);       // ~68 KB
    cudaFuncSetAttribute(encode_kernel,
                         cudaFuncAttributeMaxDynamicSharedMemorySize, smemE);
    cudaFuncSetAttribute(sim_kernel,
                         cudaFuncAttributeMaxDynamicSharedMemorySize, smemS);

    // doc encode: 262144 tokens -> 8192 blocks
    encode_kernel<<<(BB * LDOC) / TOK, 128, smemE>>>(
        dids, dmask, d_emb, dW1, db1, dW2, db2, d_lnw, d_lnb, 0);
    // query encode: 4096 tokens -> 128 blocks
    encode_kernel<<<(BB * LQ) / TOK, 128, smemE>>>(
        qids, qmask, q_emb, qW1, qb1, qW2, qb2, q_lnw, q_lnb, 1);

    dim3 gsim(BB, NCH);
    sim_kernel<<<gsim, 256, smemS>>>(dmask);
    final_kernel<<<BB, 64>>>(out);
}

// round 4
// speedup vs baseline: 3.9817x; 3.9817x over previous
#include <cuda_runtime.h>
#include <cuda_fp16.h>
#include <stdint.h>

#define HD    128
#define BB    64
#define LQ    64
#define LDOC  4096
#define NTILE 32               // 4096/128 doc tiles per batch
#define LN_EPS 1e-5f
#define NEGV  -1e30f

// ---------------- scratch (__device__ globals; no cudaMalloc) --------------
__device__ __half g_wt[4][HD * HD];                 // transposed fp16 weights
__device__ __half g_dv[(size_t)BB * LDOC * HD];     // 64 MB
__device__ __half g_qv[(size_t)BB * LQ * HD];       // 1 MB
__device__ float  g_pmax[(size_t)BB * NTILE * LQ];  // 512 KB

// ---------------- warp MMA helpers ----------------------------------------
__device__ __forceinline__ uint32_t smem_u32(const void* p) {
    uint32_t a;
    asm("{ .reg .u64 t; cvta.to.shared.u64 t, %1; cvt.u32.u64 %0, t; }"
        : "=r"(a) : "l"(p));
    return a;
}

__device__ __forceinline__ void ldsm_x4(uint32_t& r0, uint32_t& r1,
                                        uint32_t& r2, uint32_t& r3, uint32_t a) {
    asm volatile("ldmatrix.sync.aligned.m8n8.x4.shared.b16 {%0,%1,%2,%3}, [%4];"
                 : "=r"(r0), "=r"(r1), "=r"(r2), "=r"(r3) : "r"(a));
}

__device__ __forceinline__ void mma16816(float* c,
                                         uint32_t a0, uint32_t a1, uint32_t a2,
                                         uint32_t a3, uint32_t b0, uint32_t b1) {
    asm volatile(
        "mma.sync.aligned.m16n8k16.row.col.f32.f16.f16.f32 "
        "{%0,%1,%2,%3}, {%4,%5,%6,%7}, {%8,%9}, {%0,%1,%2,%3};"
        : "+f"(c[0]), "+f"(c[1]), "+f"(c[2]), "+f"(c[3])
        : "r"(a0), "r"(a1), "r"(a2), "r"(a3), "r"(b0), "r"(b1));
}

// swizzled smem offset for (row, 16B-chunk) in a [rows][256B] fp16 tile
__device__ __forceinline__ uint32_t swz(int row, int chunk) {
    return (uint32_t)(row * 256 + ((chunk ^ (row & 7)) * 16));
}

// ---------------- prep: transpose + fp16 convert of the 4 weights ----------
__global__ void prep_kernel(const float* __restrict__ dW1,
                            const float* __restrict__ dW2,
                            const float* __restrict__ qW1,
                            const float* __restrict__ qW2) {
    int i = blockIdx.x * blockDim.x + threadIdx.x;   // 65536 total
    const float* Ws[4] = {dW1, dW2, qW1, qW2};
    int mat = i >> 14, r = i & 16383, j = r >> 7, k = r & 127;
    g_wt[mat][j * HD + k] = __float2half_rn(Ws[mat][k * HD + j]);
}

// ---------------- encode ---------------------------------------------------
// SMEM: X 0..32768, W1 32768.., W2 65536.., params 98304.. (4*512B)
#define ESM_X   0
#define ESM_W1  32768
#define ESM_W2  65536
#define ESM_P   98304
#define ESM_TOTAL 100352

// One MLP layer for this warp's 16 token rows: acc = X[16,K] @ W^T -> 16x128,
// then bias+ReLU+LayerNorm (+optional mask), fp16 result written back to X.
__device__ __forceinline__ void mlp_layer(
    uint32_t Xb, uint32_t Wb,
    const float* __restrict__ sB, const float* __restrict__ sLW,
    const float* __restrict__ sLB,
    int lane, int wrow, const int* __restrict__ mrow /* null unless final */,
    char* __restrict__ smem)
{
    float acc[16][4];
#pragma unroll
    for (int t = 0; t < 16; t++) {
        acc[t][0] = 0.f; acc[t][1] = 0.f; acc[t][2] = 0.f; acc[t][3] = 0.f;
    }

    const int arow = wrow + (lane & 7) + ((lane >> 3) & 1) * 8;
    const int akc  = (lane >> 4) & 1;
    const int brow0 = (lane & 7) + ((lane >> 4) & 1) * 8;
    const int bkc  = (lane >> 3) & 1;

#pragma unroll
    for (int kk = 0; kk < 8; kk++) {
        uint32_t a0, a1, a2, a3;
        ldsm_x4(a0, a1, a2, a3, Xb + swz(arow, kk * 2 + akc));
#pragma unroll
        for (int ntp = 0; ntp < 8; ntp++) {
            const int n = ntp * 16 + brow0;
            uint32_t b0, b1, b2, b3;
            ldsm_x4(b0, b1, b2, b3, Wb + swz(n, kk * 2 + bkc));
            mma16816(acc[2 * ntp],     a0, a1, a2, a3, b0, b1);
            mma16816(acc[2 * ntp + 1], a0, a1, a2, a3, b2, b3);
        }
    }

    // epilogue: bias + ReLU, LN stats via quad reduction
    const int g = lane >> 2, q = lane & 3;
    const int r0 = wrow + g, r1 = r0 + 8;
    float s0 = 0.f, ss0 = 0.f, s1 = 0.f, ss1 = 0.f;
#pragma unroll
    for (int t = 0; t < 16; t++) {
        const float2 bc = *(const float2*)(sB + t * 8 + 2 * q);
        float v00 = fmaxf(acc[t][0] + bc.x, 0.f);
        float v01 = fmaxf(acc[t][1] + bc.y, 0.f);
        float v10 = fmaxf(acc[t][2] + bc.x, 0.f);
        float v11 = fmaxf(acc[t][3] + bc.y, 0.f);
        acc[t][0] = v00; acc[t][1] = v01; acc[t][2] = v10; acc[t][3] = v11;
        s0 += v00 + v01; ss0 += v00 * v00 + v01 * v01;
        s1 += v10 + v11; ss1 += v10 * v10 + v11 * v11;
    }
#pragma unroll
    for (int o = 1; o <= 2; o <<= 1) {
        s0  += __shfl_xor_sync(0xffffffffu, s0,  o);
        ss0 += __shfl_xor_sync(0xffffffffu, ss0, o);
        s1  += __shfl_xor_sync(0xffffffffu, s1,  o);
        ss1 += __shfl_xor_sync(0xffffffffu, ss1, o);
    }
    const float m0 = s0 * (1.0f / HD);
    const float m1 = s1 * (1.0f / HD);
    const float rs0 = rsqrtf(ss0 * (1.0f / HD) - m0 * m0 + LN_EPS);
    const float rs1 = rsqrtf(ss1 * (1.0f / HD) - m1 * m1 + LN_EPS);
    float mv0 = 1.f, mv1 = 1.f;
    if (mrow) { mv0 = (float)mrow[r0]; mv1 = (float)mrow[r1]; }

#pragma unroll
    for (int t = 0; t < 16; t++) {
        const float2 lw = *(const float2*)(sLW + t * 8 + 2 * q);
        const float2 lb = *(const float2*)(sLB + t * 8 + 2 * q);
        float y00 = ((acc[t][0] - m0) * rs0 * lw.x + lb.x) * mv0;
        float y01 = ((acc[t][1] - m0) * rs0 * lw.y + lb.y) * mv0;
        float y10 = ((acc[t][2] - m1) * rs1 * lw.x + lb.x) * mv1;
        float y11 = ((acc[t][3] - m1) * rs1 * lw.y + lb.y) * mv1;
        *(__half2*)(smem + ESM_X + swz(r0, t) + 4 * q) = __floats2half2_rn(y00, y01);
        *(__half2*)(smem + ESM_X + swz(r1, t) + 4 * q) = __floats2half2_rn(y10, y11);
    }
    __syncwarp();
}

__global__ __launch_bounds__(256)
void encode_mma(const int* __restrict__ ids, const int* __restrict__ mask,
                const float* __restrict__ emb,
                const float* __restrict__ b1, const float* __restrict__ b2,
                const float* __restrict__ lnw, const float* __restrict__ lnb,
                int mat0, int isq)
{
    extern __shared__ __align__(16) char smem[];
    const int tid = threadIdx.x, wid = tid >> 5, lane = tid & 31;
    const uint32_t sb = smem_u32(smem);
    float* sP = (float*)(smem + ESM_P);

    if (tid < 128) {
        sP[tid]       = b1[tid];
        sP[128 + tid] = b2[tid];
        sP[256 + tid] = lnw[tid];
        sP[384 + tid] = lnb[tid];
    }

    // load W1^T, W2^T (fp16 row-major 256B rows) into swizzled SMEM
    {
        const uint4* w1 = (const uint4*)g_wt[mat0];
        const uint4* w2 = (const uint4*)g_wt[mat0 + 1];
#pragma unroll
        for (int i = 0; i < 8; i++) {
            int idx = tid + i * 256;      // 2048 chunks
            int r = idx >> 4, c = idx & 15;
            *(uint4*)(smem + ESM_W1 + swz(r, c)) = w1[idx];
            *(uint4*)(smem + ESM_W2 + swz(r, c)) = w2[idx];
        }
    }

    // embedding gather -> fp16 swizzled X. 2 threads per token.
    const long tokbase = (long)blockIdx.x * 128;
    {
        const int m = tid >> 1, p = tid & 1;
        const int id = ids[tokbase + m];
        const float4* er = (const float4*)(emb + (size_t)id * HD);
#pragma unroll
        for (int c = 0; c < 8; c++) {
            float4 fa = er[p * 16 + 2 * c];
            float4 fb = er[p * 16 + 2 * c + 1];
            __half2 h0 = __floats2half2_rn(fa.x, fa.y);
            __half2 h1 = __floats2half2_rn(fa.z, fa.w);
            __half2 h2 = __floats2half2_rn(fb.x, fb.y);
            __half2 h3 = __floats2half2_rn(fb.z, fb.w);
            uint4 u = make_uint4(*(uint32_t*)&h0, *(uint32_t*)&h1,
                                 *(uint32_t*)&h2, *(uint32_t*)&h3);
            *(uint4*)(smem + ESM_X + swz(m, p * 8 + c)) = u;
        }
    }
    __syncthreads();

    const int wrow = wid * 16;
    mlp_layer(sb + ESM_X, sb + ESM_W1, sP, sP + 256, sP + 384,
              lane, wrow, nullptr, smem);
    mlp_layer(sb + ESM_X, sb + ESM_W2, sP + 128, sP + 256, sP + 384,
              lane, wrow, mask + tokbase, smem);

    __syncthreads();
    // coalesced copy X -> global (unswizzle)
    {
        __half* out = isq ? g_qv : g_dv;
        uint4* gdst = (uint4*)out + (size_t)blockIdx.x * 2048;
#pragma unroll
        for (int i = 0; i < 8; i++) {
            int idx = tid + i * 256;
            int r = idx >> 4, c = idx & 15;
            gdst[idx] = *(const uint4*)(smem + ESM_X + swz(r, c));
        }
    }
}

// ---------------- sim: per (batch, 128-doc tile) ---------------------------
// SMEM: D 0..32768 (128x256B), Q 32768..49152 (64x256B), red 49152..51200
#define SSM_D   0
#define SSM_Q   32768
#define SSM_RED 49152
#define SSM_TOTAL 51200

__global__ __launch_bounds__(256)
void sim_mma(const int* __restrict__ dmask)
{
    extern __shared__ __align__(16) char smem[];
    const int tid = threadIdx.x, wid = tid >> 5, lane = tid & 31;
    const int b = blockIdx.x, tile = blockIdx.y;
    const uint32_t sb = smem_u32(smem);

    // load doc tile (swizzled)
    {
        const uint4* src = (const uint4*)(g_dv + ((size_t)b * LDOC + (size_t)tile * 128) * HD);
#pragma unroll
        for (int i = 0; i < 8; i++) {
            int idx = tid + i * 256;
            int r = idx >> 4, c = idx & 15;
            *(uint4*)(smem + SSM_D + swz(r, c)) = src[idx];
        }
        const uint4* qs = (const uint4*)(g_qv + (size_t)b * LQ * HD);
#pragma unroll
        for (int i = 0; i < 4; i++) {
            int idx = tid + i * 256;
            int r = idx >> 4, c = idx & 15;
            *(uint4*)(smem + SSM_Q + swz(r, c)) = qs[idx];
        }
    }
    __syncthreads();

    float acc[8][4];
#pragma unroll
    for (int t = 0; t < 8; t++) {
        acc[t][0] = 0.f; acc[t][1] = 0.f; acc[t][2] = 0.f; acc[t][3] = 0.f;
    }

    const int wrow = wid * 16;
    const int arow = wrow + (lane & 7) + ((lane >> 3) & 1) * 8;
    const int akc  = (lane >> 4) & 1;
    const int brow0 = (lane & 7) + ((lane >> 4) & 1) * 8;
    const int bkc  = (lane >> 3) & 1;

#pragma unroll
    for (int kk = 0; kk < 8; kk++) {
        uint32_t a0, a1, a2, a3;
        ldsm_x4(a0, a1, a2, a3, sb + SSM_D + swz(arow, kk * 2 + akc));
#pragma unroll
        for (int ntp = 0; ntp < 4; ntp++) {
            const int n = ntp * 16 + brow0;
            uint32_t b0, b1, b2, b3;
            ldsm_x4(b0, b1, b2, b3, sb + SSM_Q + swz(n, kk * 2 + bkc));
            mma16816(acc[2 * ntp],     a0, a1, a2, a3, b0, b1);
            mma16816(acc[2 * ntp + 1], a0, a1, a2, a3, b2, b3);
        }
    }

    // penalties per doc row, then max over rows per query column
    const int g = lane >> 2, q = lane & 3;
    const int dg = b * LDOC + tile * 128 + wrow + g;
    const float p0 = (1.0f - (float)dmask[dg])     * NEGV;
    const float p1 = (1.0f - (float)dmask[dg + 8]) * NEGV;
    float* red = (float*)(smem + SSM_RED);
#pragma unroll
    for (int t = 0; t < 8; t++) {
        float v0 = fmaxf(acc[t][0] + p0, acc[t][2] + p1);
        float v1 = fmaxf(acc[t][1] + p0, acc[t][3] + p1);
#pragma unroll
        for (int o = 4; o <= 16; o <<= 1) {
            v0 = fmaxf(v0, __shfl_xor_sync(0xffffffffu, v0, o));
            v1 = fmaxf(v1, __shfl_xor_sync(0xffffffffu, v1, o));
        }
        if (lane < 4)
            *(float2*)(red + wid * 64 + t * 8 + 2 * lane) = make_float2(v0, v1);
    }
    __syncthreads();
    if (tid < 64) {
        float m = red[tid];
#pragma unroll
        for (int w = 1; w < 8; w++) m = fmaxf(m, red[w * 64 + tid]);
        g_pmax[((size_t)b * NTILE + tile) * LQ + tid] = m;
    }
}

// ---------------- final: max over tiles, sum over queries ------------------
__global__ void final_k(float* __restrict__ out)
{
    const int b = blockIdx.x, q = threadIdx.x;   // 64 threads
    float m = -3.0e38f;
#pragma unroll
    for (int t = 0; t < NTILE; t++)
        m = fmaxf(m, g_pmax[((size_t)b * NTILE + t) * LQ + q]);
    float s = m;
#pragma unroll
    for (int o = 16; o > 0; o >>= 1) s += __shfl_xor_sync(0xffffffffu, s, o);
    __shared__ float sp[2];
    if ((q & 31) == 0) sp[q >> 5] = s;
    __syncthreads();
    if (q == 0) out[b] = sp[0] + sp[1];
}

// ---------------- launch ---------------------------------------------------
extern "C" void kernel_launch(void* const* d_in, const int* in_sizes, int n_in,
                              void* d_out, int out_size)
{
    const int*   qids  = (const int*)d_in[0];
    const int*   dids  = (const int*)d_in[1];
    const int*   qmask = (const int*)d_in[2];
    const int*   dmask = (const int*)d_in[3];
    const float* q_emb = (const float*)d_in[4];
    const float* qW1   = (const float*)d_in[5];
    const float* qb1   = (const float*)d_in[6];
    const float* qW2   = (const float*)d_in[7];
    const float* qb2   = (const float*)d_in[8];
    const float* q_lnw = (const float*)d_in[9];
    const float* q_lnb = (const float*)d_in[10];
    const float* d_emb = (const float*)d_in[11];
    const float* dW1   = (const float*)d_in[12];
    const float* db1   = (const float*)d_in[13];
    const float* dW2   = (const float*)d_in[14];
    const float* db2   = (const float*)d_in[15];
    const float* d_lnw = (const float*)d_in[16];
    const float* d_lnb = (const float*)d_in[17];
    float* out = (float*)d_out;

    cudaFuncSetAttribute(encode_mma,
        cudaFuncAttributeMaxDynamicSharedMemorySize, ESM_TOTAL);
    cudaFuncSetAttribute(sim_mma,
        cudaFuncAttributeMaxDynamicSharedMemorySize, SSM_TOTAL);

    prep_kernel<<<256, 256>>>(dW1, dW2, qW1, qW2);

    encode_mma<<<(BB * LDOC) / 128, 256, ESM_TOTAL>>>(
        dids, dmask, d_emb, db1, db2, d_lnw, d_lnb, 0, 0);
    encode_mma<<<(BB * LQ) / 128, 256, ESM_TOTAL>>>(
        qids, qmask, q_emb, qb1, qb2, q_lnw, q_lnb, 2, 1);

    dim3 gsim(BB, NTILE);
    sim_mma<<<gsim, 256, SSM_TOTAL>>>(dmask);
    final_k<<<BB, 64>>>(out);
}

// round 5
// speedup vs baseline: 5.1436x; 1.2918x over previous
#include <cuda_runtime.h>
#include <cuda_fp16.h>
#include <stdint.h>

#define HD    128
#define BB    64
#define LQ    64
#define LDOC  4096
#define NTILE 32               // 4096/128 doc tiles per batch
#define LN_EPS 1e-5f
#define NEGV  -1e30f

// ---------------- scratch (__device__ globals; no cudaMalloc) --------------
__device__ __half g_wt[4][HD * HD];                 // transposed fp16 weights
__device__ __half g_qv[(size_t)BB * LQ * HD];       // 1 MB, stored SWIZZLED
__device__ float  g_pmax[(size_t)BB * NTILE * LQ];  // 512 KB

// ---------------- warp MMA helpers ----------------------------------------
__device__ __forceinline__ uint32_t smem_u32(const void* p) {
    uint32_t a;
    asm("{ .reg .u64 t; cvta.to.shared.u64 t, %1; cvt.u32.u64 %0, t; }"
        : "=r"(a) : "l"(p));
    return a;
}

__device__ __forceinline__ void ldsm_x4(uint32_t& r0, uint32_t& r1,
                                        uint32_t& r2, uint32_t& r3, uint32_t a) {
    asm volatile("ldmatrix.sync.aligned.m8n8.x4.shared.b16 {%0,%1,%2,%3}, [%4];"
                 : "=r"(r0), "=r"(r1), "=r"(r2), "=r"(r3) : "r"(a));
}

__device__ __forceinline__ void mma16816(float* c,
                                         uint32_t a0, uint32_t a1, uint32_t a2,
                                         uint32_t a3, uint32_t b0, uint32_t b1) {
    asm volatile(
        "mma.sync.aligned.m16n8k16.row.col.f32.f16.f16.f32 "
        "{%0,%1,%2,%3}, {%4,%5,%6,%7}, {%8,%9}, {%0,%1,%2,%3};"
        : "+f"(c[0]), "+f"(c[1]), "+f"(c[2]), "+f"(c[3])
        : "r"(a0), "r"(a1), "r"(a2), "r"(a3), "r"(b0), "r"(b1));
}

// swizzled smem offset for (row, 16B-chunk) in a [rows][256B] fp16 tile
__device__ __forceinline__ uint32_t swz(int row, int chunk) {
    return (uint32_t)(row * 256 + ((chunk ^ (row & 7)) * 16));
}

// ---------------- prep: transpose + fp16 convert of the 4 weights ----------
__global__ void prep_kernel(const float* __restrict__ dW1,
                            const float* __restrict__ dW2,
                            const float* __restrict__ qW1,
                            const float* __restrict__ qW2) {
    int i = blockIdx.x * blockDim.x + threadIdx.x;   // 65536 total
    const float* Ws[4] = {dW1, dW2, qW1, qW2};
    int mat = i >> 14, r = i & 16383, j = r >> 7, k = r & 127;
    g_wt[mat][j * HD + k] = __float2half_rn(Ws[mat][k * HD + j]);
}

// ---------------- fused encode (+maxsim for docs) --------------------------
// 128 threads = 4 warps, M=32 token rows per warp.
// SMEM: X 0..32K, WA 32K..64K (W1, then Q tile), WB 64K..96K (W2),
//       P 96K+2304.. params, RED reduction
#define ESM_X   0
#define ESM_WA  32768
#define ESM_WB  65536
#define ESM_P   98304
#define ESM_RED 100352
#define ESM_TOTAL 101376

// One MLP layer for this warp's 32 token rows:
// acc = X[32,128] @ W^T -> 32x128, bias+ReLU+LayerNorm (+opt mask), back to X.
__device__ __forceinline__ void mlp_layer32(
    uint32_t Xb, uint32_t Wb,
    const float* __restrict__ sB, const float* __restrict__ sLW,
    const float* __restrict__ sLB,
    int lane, int wrow, const int* __restrict__ mrow,
    char* __restrict__ smem)
{
    float acc[2][16][4];
#pragma unroll
    for (int mt = 0; mt < 2; mt++)
#pragma unroll
        for (int nt = 0; nt < 16; nt++) {
            acc[mt][nt][0] = 0.f; acc[mt][nt][1] = 0.f;
            acc[mt][nt][2] = 0.f; acc[mt][nt][3] = 0.f;
        }

    const int arow  = wrow + (lane & 7) + ((lane >> 3) & 1) * 8;
    const int akc   = (lane >> 4) & 1;
    const int brow0 = (lane & 7) + ((lane >> 4) & 1) * 8;
    const int bkc   = (lane >> 3) & 1;

#pragma unroll
    for (int kk = 0; kk < 8; kk++) {
        uint32_t a0[4], a1[4];
        ldsm_x4(a0[0], a0[1], a0[2], a0[3], Xb + swz(arow,      kk * 2 + akc));
        ldsm_x4(a1[0], a1[1], a1[2], a1[3], Xb + swz(arow + 16, kk * 2 + akc));
#pragma unroll
        for (int nt2 = 0; nt2 < 8; nt2++) {
            uint32_t b0, b1, b2, b3;
            ldsm_x4(b0, b1, b2, b3, Wb + swz(nt2 * 16 + brow0, kk * 2 + bkc));
            mma16816(acc[0][2 * nt2],     a0[0], a0[1], a0[2], a0[3], b0, b1);
            mma16816(acc[0][2 * nt2 + 1], a0[0], a0[1], a0[2], a0[3], b2, b3);
            mma16816(acc[1][2 * nt2],     a1[0], a1[1], a1[2], a1[3], b0, b1);
            mma16816(acc[1][2 * nt2 + 1], a1[0], a1[1], a1[2], a1[3], b2, b3);
        }
    }

    // epilogue: bias + ReLU + LN. 4 rows per thread: j=(mt,h) -> row
    const int g = lane >> 2, q4 = lane & 3;
    int r4[4] = {wrow + g, wrow + g + 8, wrow + 16 + g, wrow + 24 + g};
    float s[4] = {0.f, 0.f, 0.f, 0.f}, ss[4] = {0.f, 0.f, 0.f, 0.f};
#pragma unroll
    for (int nt = 0; nt < 16; nt++) {
        const float2 bc = *(const float2*)(sB + nt * 8 + 2 * q4);
#pragma unroll
        for (int j = 0; j < 4; j++) {
            const int mt = j >> 1, h = j & 1;
            float v0 = fmaxf(acc[mt][nt][2 * h]     + bc.x, 0.f);
            float v1 = fmaxf(acc[mt][nt][2 * h + 1] + bc.y, 0.f);
            acc[mt][nt][2 * h] = v0; acc[mt][nt][2 * h + 1] = v1;
            s[j] += v0 + v1; ss[j] += v0 * v0 + v1 * v1;
        }
    }
#pragma unroll
    for (int o = 1; o <= 2; o <<= 1)
#pragma unroll
        for (int j = 0; j < 4; j++) {
            s[j]  += __shfl_xor_sync(0xffffffffu, s[j],  o);
            ss[j] += __shfl_xor_sync(0xffffffffu, ss[j], o);
        }
    float mean[4], rstd[4], mv[4];
#pragma unroll
    for (int j = 0; j < 4; j++) {
        mean[j] = s[j] * (1.0f / HD);
        rstd[j] = rsqrtf(ss[j] * (1.0f / HD) - mean[j] * mean[j] + LN_EPS);
        mv[j]   = mrow ? (float)mrow[r4[j]] : 1.0f;
    }
#pragma unroll
    for (int nt = 0; nt < 16; nt++) {
        const float2 lw = *(const float2*)(sLW + nt * 8 + 2 * q4);
        const float2 lb = *(const float2*)(sLB + nt * 8 + 2 * q4);
#pragma unroll
        for (int j = 0; j < 4; j++) {
            const int mt = j >> 1, h = j & 1;
            float y0 = ((acc[mt][nt][2 * h]     - mean[j]) * rstd[j] * lw.x + lb.x) * mv[j];
            float y1 = ((acc[mt][nt][2 * h + 1] - mean[j]) * rstd[j] * lw.y + lb.y) * mv[j];
            *(__half2*)(smem + ESM_X + swz(r4[j], nt) + 4 * q4) =
                __floats2half2_rn(y0, y1);
        }
    }
    __syncwarp();
}

__global__ __launch_bounds__(128)
void encode_fused(const int* __restrict__ ids, const int* __restrict__ mask,
                  const float* __restrict__ emb,
                  const float* __restrict__ b1, const float* __restrict__ b2,
                  const float* __restrict__ lnw, const float* __restrict__ lnb,
                  const int* __restrict__ dmask, int mat0, int isq)
{
    extern __shared__ __align__(16) char smem[];
    const int tid = threadIdx.x, wid = tid >> 5, lane = tid & 31;
    const uint32_t sb = smem_u32(smem);
    float* sP = (float*)(smem + ESM_P);

    sP[tid]       = b1[tid];
    sP[128 + tid] = b2[tid];
    sP[256 + tid] = lnw[tid];
    sP[384 + tid] = lnb[tid];

    // W1 -> WA, W2 -> WB (swizzled)
    {
        const uint4* w1 = (const uint4*)g_wt[mat0];
        const uint4* w2 = (const uint4*)g_wt[mat0 + 1];
#pragma unroll
        for (int i = 0; i < 16; i++) {
            int idx = tid + i * 128;       // 2048 chunks
            int r = idx >> 4, c = idx & 15;
            *(uint4*)(smem + ESM_WA + swz(r, c)) = w1[idx];
            *(uint4*)(smem + ESM_WB + swz(r, c)) = w2[idx];
        }
    }

    // embedding gather: 1 thread per token
    {
        const int id = ids[(size_t)blockIdx.x * 128 + tid];
        const float4* er = (const float4*)(emb + (size_t)id * HD);
#pragma unroll
        for (int c = 0; c < 16; c++) {
            float4 fa = er[2 * c], fb = er[2 * c + 1];
            __half2 h0 = __floats2half2_rn(fa.x, fa.y);
            __half2 h1 = __floats2half2_rn(fa.z, fa.w);
            __half2 h2 = __floats2half2_rn(fb.x, fb.y);
            __half2 h3 = __floats2half2_rn(fb.z, fb.w);
            *(uint4*)(smem + ESM_X + swz(tid, c)) =
                make_uint4(*(uint32_t*)&h0, *(uint32_t*)&h1,
                           *(uint32_t*)&h2, *(uint32_t*)&h3);
        }
    }
    __syncthreads();

    const int wrow = wid * 32;
    mlp_layer32(sb + ESM_X, sb + ESM_WA, sP, sP + 256, sP + 384,
                lane, wrow, nullptr, smem);
    __syncthreads();   // all warps done with W1

    if (!isq) {
        // stage this batch's query tile (already swizzled in g_qv) into WA
        const int b = blockIdx.x >> 5;
        const uint4* qs = (const uint4*)(g_qv + (size_t)b * LQ * HD);
#pragma unroll
        for (int i = 0; i < 8; i++)
            ((uint4*)(smem + ESM_WA))[tid + i * 128] = qs[tid + i * 128];
    }

    mlp_layer32(sb + ESM_X, sb + ESM_WB, sP + 128, sP + 256, sP + 384,
                lane, wrow, isq ? (mask + (size_t)blockIdx.x * 128) : nullptr,
                smem);
    __syncthreads();   // X final + Q tile visible

    if (isq) {
        // store raw swizzled bytes; per-64-row halves stay valid tiles
        uint4* gdst = (uint4*)g_qv + (size_t)blockIdx.x * 2048;
#pragma unroll
        for (int i = 0; i < 16; i++)
            gdst[tid + i * 128] = ((const uint4*)(smem + ESM_X))[tid + i * 128];
        return;
    }

    // ---- fused maxsim: D[128 docs] x Q[64 queries], K=128 ----
    float sa[2][8][4];
#pragma unroll
    for (int mt = 0; mt < 2; mt++)
#pragma unroll
        for (int nt = 0; nt < 8; nt++) {
            sa[mt][nt][0] = 0.f; sa[mt][nt][1] = 0.f;
            sa[mt][nt][2] = 0.f; sa[mt][nt][3] = 0.f;
        }
    {
        const int arow  = wrow + (lane & 7) + ((lane >> 3) & 1) * 8;
        const int akc   = (lane >> 4) & 1;
        const int brow0 = (lane & 7) + ((lane >> 4) & 1) * 8;
        const int bkc   = (lane >> 3) & 1;
#pragma unroll
        for (int kk = 0; kk < 8; kk++) {
            uint32_t a0[4], a1[4];
            ldsm_x4(a0[0], a0[1], a0[2], a0[3],
                    sb + ESM_X + swz(arow,      kk * 2 + akc));
            ldsm_x4(a1[0], a1[1], a1[2], a1[3],
                    sb + ESM_X + swz(arow + 16, kk * 2 + akc));
#pragma unroll
            for (int nt2 = 0; nt2 < 4; nt2++) {
                uint32_t b0, b1, b2, b3;
                ldsm_x4(b0, b1, b2, b3,
                        sb + ESM_WA + swz(nt2 * 16 + brow0, kk * 2 + bkc));
                mma16816(sa[0][2 * nt2],     a0[0], a0[1], a0[2], a0[3], b0, b1);
                mma16816(sa[0][2 * nt2 + 1], a0[0], a0[1], a0[2], a0[3], b2, b3);
                mma16816(sa[1][2 * nt2],     a1[0], a1[1], a1[2], a1[3], b0, b1);
                mma16816(sa[1][2 * nt2 + 1], a1[0], a1[1], a1[2], a1[3], b2, b3);
            }
        }
    }

    // penalties + max over this warp's 32 doc rows
    const int g = lane >> 2;
    int r4[4] = {wrow + g, wrow + g + 8, wrow + 16 + g, wrow + 24 + g};
    float p[4];
#pragma unroll
    for (int j = 0; j < 4; j++)
        p[j] = (1.0f - (float)dmask[(size_t)blockIdx.x * 128 + r4[j]]) * NEGV;

    float* red = (float*)(smem + ESM_RED);
#pragma unroll
    for (int nt = 0; nt < 8; nt++) {
        float v0 = -3.0e38f, v1 = -3.0e38f;
#pragma unroll
        for (int j = 0; j < 4; j++) {
            const int mt = j >> 1, h = j & 1;
            v0 = fmaxf(v0, sa[mt][nt][2 * h]     + p[j]);
            v1 = fmaxf(v1, sa[mt][nt][2 * h + 1] + p[j]);
        }
#pragma unroll
        for (int o = 4; o <= 16; o <<= 1) {
            v0 = fmaxf(v0, __shfl_xor_sync(0xffffffffu, v0, o));
            v1 = fmaxf(v1, __shfl_xor_sync(0xffffffffu, v1, o));
        }
        if (lane < 4)
            *(float2*)(red + wid * 64 + nt * 8 + 2 * lane) = make_float2(v0, v1);
    }
    __syncthreads();
    if (tid < 64) {
        float m = red[tid];
#pragma unroll
        for (int w = 1; w < 4; w++) m = fmaxf(m, red[w * 64 + tid]);
        g_pmax[(size_t)blockIdx.x * 64 + tid] = m;
    }
}

// ---------------- final: max over tiles, sum over queries ------------------
__global__ void final_k(float* __restrict__ out)
{
    const int b = blockIdx.x, q = threadIdx.x;   // 64 threads
    float m = -3.0e38f;
#pragma unroll
    for (int t = 0; t < NTILE; t++)
        m = fmaxf(m, g_pmax[((size_t)b * NTILE + t) * LQ + q]);
    float s = m;
#pragma unroll
    for (int o = 16; o > 0; o >>= 1) s += __shfl_xor_sync(0xffffffffu, s, o);
    __shared__ float sp[2];
    if ((q & 31) == 0) sp[q >> 5] = s;
    __syncthreads();
    if (q == 0) out[b] = sp[0] + sp[1];
}

// ---------------- launch ---------------------------------------------------
extern "C" void kernel_launch(void* const* d_in, const int* in_sizes, int n_in,
                              void* d_out, int out_size)
{
    const int*   qids  = (const int*)d_in[0];
    const int*   dids  = (const int*)d_in[1];
    const int*   qmask = (const int*)d_in[2];
    const int*   dmask = (const int*)d_in[3];
    const float* q_emb = (const float*)d_in[4];
    const float* qW1   = (const float*)d_in[5];
    const float* qb1   = (const float*)d_in[6];
    const float* qW2   = (const float*)d_in[7];
    const float* qb2   = (const float*)d_in[8];
    const float* q_lnw = (const float*)d_in[9];
    const float* q_lnb = (const float*)d_in[10];
    const float* d_emb = (const float*)d_in[11];
    const float* dW1   = (const float*)d_in[12];
    const float* db1   = (const float*)d_in[13];
    const float* dW2   = (const float*)d_in[14];
    const float* db2   = (const float*)d_in[15];
    const float* d_lnw = (const float*)d_in[16];
    const float* d_lnb = (const float*)d_in[17];
    float* out = (float*)d_out;

    cudaFuncSetAttribute(encode_fused,
        cudaFuncAttributeMaxDynamicSharedMemorySize, ESM_TOTAL);

    prep_kernel<<<256, 256>>>(dW1, dW2, qW1, qW2);

    // queries first (writes g_qv, swizzled)
    encode_fused<<<(BB * LQ) / 128, 128, ESM_TOTAL>>>(
        qids, qmask, q_emb, qb1, qb2, q_lnw, q_lnb, dmask, 2, 1);
    // docs with fused maxsim (reads g_qv, writes g_pmax)
    encode_fused<<<(BB * LDOC) / 128, 128, ESM_TOTAL>>>(
        dids, dmask, d_emb, db1, db2, d_lnw, d_lnb, dmask, 0, 0);

    final_k<<<BB, 64>>>(out);
}